// round 16
// baseline (speedup 1.0000x reference)
#include <cuda_runtime.h>

// Problem constants (fixed-shape problem)
#define NB 1024
#define ND 64
#define NL 8
#define NK 16
#define DS 68                 // smem row stride in floats (16B-aligned, de-conflicted)
#define MAT (ND * ND)         // 4096
#define PLANE (NB * ND * ND)  // 4,194,304

// Ping-pong scratch for intermediate rho (re plane then im plane). 32 MB static.
__device__ float g_qhmm_scratch[2 * NB * ND * ND];

typedef unsigned long long ull;

union Q4 { float4 v; ull u[2]; float f[4]; };

__device__ __forceinline__ ull dup2(float x) {
    ull r; asm("mov.b64 %0, {%1, %2};" : "=l"(r) : "f"(x), "f"(x)); return r;
}
__device__ __forceinline__ void fma2(ull& d, ull a, ull b) {
    asm("fma.rn.f32x2 %0, %1, %2, %0;" : "+l"(d) : "l"(a), "l"(b));
}

// One layer, one ROW-HALF of one batch per block (grid = 2*NB):
//   rho_out[rows half] = sum_k ( K_k @ rho @ K_k^H )[rows half]
// Thread map: 256 threads as 16(ty: 2-row groups) x 16(tx: 4-col groups).
// Each thread owns a 2x4 complex tile.
//   Phase A: T[i][l] = sum_j K[i][j] rho[j][l]   (i in our 32-row half; T row-major in smem)
//   Phase B: C[i][m] += sum_l T[i][l] conj(K[m][l])  (accumulated in regs across k)
// Negations are eliminated: phase A keeps Kr*rr and Ki*ri in separate accumulators
// (one fused subtract per k), phase B keeps ci+ = Ti*Kr and ci- = Tr*Ki separate
// across all k (one fused subtract at the end). fma pipe does only useful FMA2s.
__global__ void __launch_bounds__(256, 2)
qhmm_layer_kernel(const float* __restrict__ rin_re, const float* __restrict__ rin_im,
                  const float* __restrict__ kl_re,  const float* __restrict__ kl_im,
                  float* __restrict__ rout_re, float* __restrict__ rout_im)
{
    extern __shared__ float s[];
    float* s_rr = s;                 // rho real   [j][l], stride DS (full 64x64)
    float* s_ri = s_rr + ND * DS;    // rho imag
    float* s_kr = s_ri + ND * DS;    // Kt real    [x][m] = K[m][x]  (full, transposed)
    float* s_ki = s_kr + ND * DS;    // Kt imag
    float* s_tr = s_ki + ND * DS;    // T real     [r][l], r = local row 0..31
    float* s_ti = s_tr + 32 * DS;    // T imag

    const int bid   = blockIdx.x;
    const int b     = bid >> 1;
    const int rbase = (bid & 1) * 32;   // global row base of this half
    const int tid = threadIdx.x;
    const int tx  = tid & 15;
    const int ty  = tid >> 4;
    const int r0  = 2 * ty;   // local output row base (0..30)
    const int c0  = 4 * tx;   // output col base

    // Load full rho for this batch into smem (coalesced reads, stride-DS rows).
    {
        const float* gr = rin_re + b * MAT;
        const float* gi = rin_im + b * MAT;
        #pragma unroll
        for (int e = tid; e < MAT; e += 256) {
            int i = e >> 6, j = e & 63;
            s_rr[i * DS + j] = gr[e];
            s_ri[i * DS + j] = gi[e];
        }
    }

    // Output accumulators: C[r0+ii][c0 + 2p + {0,1}], packed f32x2 along columns.
    // cr = real; cip/cim = imag split so no negation is needed in the hot loop.
    ull cr[2][2], cip[2][2], cim[2][2];
    #pragma unroll
    for (int a = 0; a < 2; a++)
        #pragma unroll
        for (int p = 0; p < 2; p++) { cr[a][p] = 0ull; cip[a][p] = 0ull; cim[a][p] = 0ull; }

    const ull NEG1 = dup2(-1.0f);

    for (int k = 0; k < NK; k++) {
        __syncthreads();  // previous phase B done reading s_k* / s_t*
        // Stage K_k transposed: Kt[x][m] = K[m][x]
        {
            const float* gkr = kl_re + k * MAT;
            const float* gki = kl_im + k * MAT;
            #pragma unroll
            for (int e = tid; e < MAT; e += 256) {
                int i = e >> 6, j = e & 63;
                s_kr[j * DS + i] = gkr[e];
                s_ki[j * DS + i] = gki[e];
            }
        }
        __syncthreads();

        // ---- Phase A: T[i][l] = sum_j K[i][j] * rho[j][l], i = rbase+r0+{0,1} ----
        ull trp[2][2], trm[2][2], tim[2][2];
        #pragma unroll
        for (int a = 0; a < 2; a++)
            #pragma unroll
            for (int p = 0; p < 2; p++) { trp[a][p] = 0ull; trm[a][p] = 0ull; tim[a][p] = 0ull; }

        const float* kc_r = s_kr + rbase + r0;   // Kt[j][rbase+r0 ..] = K[rbase+r0..][j]
        const float* kc_i = s_ki + rbase + r0;
        #pragma unroll 4
        for (int j = 0; j < ND; j++) {
            float2 ar2 = *(const float2*)(kc_r + j * DS);  // K[row0..row1][j] (broadcast)
            float2 ai2 = *(const float2*)(kc_i + j * DS);
            Q4 br, bi;
            br.v = *(const float4*)(s_rr + j * DS + c0);   // rho[j][c0..c0+3] (vector)
            bi.v = *(const float4*)(s_ri + j * DS + c0);
            {   // ii = 0
                ull a_r = dup2(ar2.x), a_i = dup2(ai2.x);
                fma2(trp[0][0], a_r, br.u[0]); fma2(trp[0][1], a_r, br.u[1]);
                fma2(trm[0][0], a_i, bi.u[0]); fma2(trm[0][1], a_i, bi.u[1]);
                fma2(tim[0][0], a_r, bi.u[0]); fma2(tim[0][1], a_r, bi.u[1]);
                fma2(tim[0][0], a_i, br.u[0]); fma2(tim[0][1], a_i, br.u[1]);
            }
            {   // ii = 1
                ull a_r = dup2(ar2.y), a_i = dup2(ai2.y);
                fma2(trp[1][0], a_r, br.u[0]); fma2(trp[1][1], a_r, br.u[1]);
                fma2(trm[1][0], a_i, bi.u[0]); fma2(trm[1][1], a_i, bi.u[1]);
                fma2(tim[1][0], a_r, bi.u[0]); fma2(tim[1][1], a_r, bi.u[1]);
                fma2(tim[1][0], a_i, br.u[0]); fma2(tim[1][1], a_i, br.u[1]);
            }
        }
        // tr = trp - trm (fused), then store T row-major as float4
        #pragma unroll
        for (int ii = 0; ii < 2; ii++) {
            fma2(trp[ii][0], trm[ii][0], NEG1);
            fma2(trp[ii][1], trm[ii][1], NEG1);
            Q4 o;
            o.u[0] = trp[ii][0]; o.u[1] = trp[ii][1];
            *(float4*)(s_tr + (r0 + ii) * DS + c0) = o.v;
            o.u[0] = tim[ii][0]; o.u[1] = tim[ii][1];
            *(float4*)(s_ti + (r0 + ii) * DS + c0) = o.v;
        }
        __syncthreads();

        // ---- Phase B: C[i][m] += sum_l T[i][l] * conj(K[m][l]) ----
        #pragma unroll 2
        for (int l = 0; l < ND; l += 4) {
            Q4 tr0, tr1, ti0, ti1;
            tr0.v = *(const float4*)(s_tr + (r0    ) * DS + l);  // T[row0][l..l+3] (broadcast)
            tr1.v = *(const float4*)(s_tr + (r0 + 1) * DS + l);
            ti0.v = *(const float4*)(s_ti + (r0    ) * DS + l);
            ti1.v = *(const float4*)(s_ti + (r0 + 1) * DS + l);
            #pragma unroll
            for (int q = 0; q < 4; q++) {
                Q4 kr, ki;
                kr.v = *(const float4*)(s_kr + (l + q) * DS + c0);  // K[c0..c0+3][l+q] (vector)
                ki.v = *(const float4*)(s_ki + (l + q) * DS + c0);
                {   // ii = 0
                    ull t_r = dup2(tr0.f[q]), t_i = dup2(ti0.f[q]);
                    fma2(cr[0][0],  t_r, kr.u[0]); fma2(cr[0][1],  t_r, kr.u[1]);
                    fma2(cr[0][0],  t_i, ki.u[0]); fma2(cr[0][1],  t_i, ki.u[1]);
                    fma2(cip[0][0], t_i, kr.u[0]); fma2(cip[0][1], t_i, kr.u[1]);
                    fma2(cim[0][0], t_r, ki.u[0]); fma2(cim[0][1], t_r, ki.u[1]);
                }
                {   // ii = 1
                    ull t_r = dup2(tr1.f[q]), t_i = dup2(ti1.f[q]);
                    fma2(cr[1][0],  t_r, kr.u[0]); fma2(cr[1][1],  t_r, kr.u[1]);
                    fma2(cr[1][0],  t_i, ki.u[0]); fma2(cr[1][1],  t_i, ki.u[1]);
                    fma2(cip[1][0], t_i, kr.u[0]); fma2(cip[1][1], t_i, kr.u[1]);
                    fma2(cim[1][0], t_r, ki.u[0]); fma2(cim[1][1], t_r, ki.u[1]);
                }
            }
        }
    }

    // ci = cip - cim (fused), write result (float4 per row per plane)
    float* orr = rout_re + b * MAT;
    float* ori = rout_im + b * MAT;
    #pragma unroll
    for (int ii = 0; ii < 2; ii++) {
        fma2(cip[ii][0], cim[ii][0], NEG1);
        fma2(cip[ii][1], cim[ii][1], NEG1);
        int off = (rbase + r0 + ii) * ND + c0;
        Q4 o;
        o.u[0] = cr[ii][0];  o.u[1] = cr[ii][1];
        *(float4*)(orr + off) = o.v;
        o.u[0] = cip[ii][0]; o.u[1] = cip[ii][1];
        *(float4*)(ori + off) = o.v;
    }
}

extern "C" void kernel_launch(void* const* d_in, const int* in_sizes, int n_in,
                              void* d_out, int out_size)
{
    const float* st_re = (const float*)d_in[0];  // [B,D,D]
    const float* st_im = (const float*)d_in[1];  // [B,D,D]
    const float* kr_re = (const float*)d_in[2];  // [L,K,D,D]
    const float* kr_im = (const float*)d_in[3];  // [L,K,D,D]

    float* out    = (float*)d_out;   // [2,B,D,D]
    float* out_re = out;
    float* out_im = out + PLANE;

    float* scr = nullptr;
    cudaGetSymbolAddress((void**)&scr, g_qhmm_scratch);
    float* scr_re = scr;
    float* scr_im = scr + PLANE;

    // 4 full planes (rho re/im, Kt re/im) + 2 half planes (T re/im)
    const size_t smem = (size_t)(4 * ND * DS + 2 * 32 * DS) * sizeof(float);  // 87040 B
    cudaFuncSetAttribute(qhmm_layer_kernel,
                         cudaFuncAttributeMaxDynamicSharedMemorySize, (int)smem);

    const float* in_re = st_re;
    const float* in_im = st_im;
    for (int l = 0; l < NL; l++) {
        // Even layers -> scratch, odd layers -> d_out. NL=8 => final (l=7) lands in d_out.
        float* o_re = (l & 1) ? out_re : scr_re;
        float* o_im = (l & 1) ? out_im : scr_im;
        qhmm_layer_kernel<<<2 * NB, 256, smem>>>(
            in_re, in_im,
            kr_re + (size_t)l * NK * MAT,
            kr_im + (size_t)l * NK * MAT,
            o_re, o_im);
        in_re = o_re;
        in_im = o_im;
    }
}